// round 10
// baseline (speedup 1.0000x reference)
#include <cuda_runtime.h>
#include <cuda_fp16.h>
#include <cstdint>

#define BB  2
#define SS  2048
#define DD  1024
#define HH  16
#define DHH 64

// Scratch (allocation-free rule: __device__ globals)
__device__ float g_QH[BB*HH*SS*DHH];   // [B,H,S,DH]
__device__ float g_KH[BB*HH*SS*DHH];   // [B,H,S,DH]
__device__ float g_VT[BB*HH*DHH*SS];   // [B,H,DH,S]  (transposed V)
__device__ float g_O [BB*SS*DD];       // [B,S,D]
__device__ float g_S [BB*HH*SS];       // per-row 1/sum for attn normalization

// ---------------------------------------------------------------------------
__device__ __forceinline__ unsigned f2tf(float f) {
    unsigned u;
    asm("cvt.rna.tf32.f32 %0, %1;" : "=r"(u) : "f"(f));
    return u;
}
__device__ __forceinline__ unsigned h2(float a, float b) {
    __half2 h = __floats2half2_rn(a, b);
    return *(unsigned*)&h;
}

__device__ __forceinline__ void mma8(float c[4],
                                     unsigned a0, unsigned a1, unsigned a2, unsigned a3,
                                     unsigned b0, unsigned b1) {
    asm("mma.sync.aligned.m16n8k8.row.col.f32.tf32.tf32.f32 "
        "{%0,%1,%2,%3},{%4,%5,%6,%7},{%8,%9},{%0,%1,%2,%3};"
        : "+f"(c[0]), "+f"(c[1]), "+f"(c[2]), "+f"(c[3])
        : "r"(a0), "r"(a1), "r"(a2), "r"(a3), "r"(b0), "r"(b1));
}
__device__ __forceinline__ void mma16h(float c[4],
                                       unsigned a0, unsigned a1, unsigned a2, unsigned a3,
                                       unsigned b0, unsigned b1) {
    asm("mma.sync.aligned.m16n8k16.row.col.f32.f16.f16.f32 "
        "{%0,%1,%2,%3},{%4,%5,%6,%7},{%8,%9},{%0,%1,%2,%3};"
        : "+f"(c[0]), "+f"(c[1]), "+f"(c[2]), "+f"(c[3])
        : "r"(a0), "r"(a1), "r"(a2), "r"(a3), "r"(b0), "r"(b1));
}

// ===========================================================================
// FUSED ATTENTION (single pass, fp16 mma, no-max softmax):
//   p = exp(score) (unnormalized) -> attn; s = row sum; O = (p.V) / s
// attn is later scaled by 1/s in scale_kernel.
//
// fp16 fragment plane layout, per 16-k block kb, uint = half2(k, k+1):
//   A plane e = rowhalf + 2*khalf:  value[lane] = A(16g + lane/4 + 8*rowhalf,
//                                     kb*16 + khalf*8 + 2*(lane%4) + {0,1})
//   B plane e = khalf:              value[lane] = B(8g + lane/4, same k)
//
// Dyn smem (bytes):
//   QA [4][8][4][32]u      @0      16384   (Q 128x64, resident)
//   KB [2][2][8][4][32]u   @16384  16384   (K tiles, double buffered)
//   VB [2][2][8][4][32]u   @32768  16384   (V^T tiles, double buffered)
//   Ps [4][8][4][32]u      @49152  16384   (fp16 P tile, fragment-native)
//   red float[4][128]      @49152  (overlay on Ps, used after main loop)
//   sF  float[128]         @65536  512     (1/s per row)
// total 66048 -> 2 CTAs/SM
// ===========================================================================
#define SMEM_FUSED 66048

__global__ __launch_bounds__(256, 2) void fused_attn_kernel(
    const int* __restrict__ mask, float* __restrict__ attn)
{
    extern __shared__ char sm_raw[];
    unsigned* QA  = (unsigned*)(sm_raw);           // [((e*8+g)*4+kb)*32+lane]
    unsigned* KBu = (unsigned*)(sm_raw + 16384);   // + buf*2048 uints
    unsigned* VBu = (unsigned*)(sm_raw + 32768);
    unsigned* Ps  = (unsigned*)(sm_raw + 49152);
    float*    red = (float*)   (sm_raw + 49152);   // overlay (post-loop)
    float*    sF  = (float*)   (sm_raw + 65536);

    const int tid  = threadIdx.x;
    const int lane = tid & 31;
    const int warp = tid >> 5;
    const int wm = warp & 1;       // 64-row half
    const int wn = warp >> 1;      // 16-col group
    const int bh = blockIdx.y;
    const int m0 = blockIdx.x * 128;
    const float* Qg = g_QH + (size_t)bh * SS * DHH + (size_t)m0 * DHH;
    const float* Kg = g_KH + (size_t)bh * SS * DHH;
    const float* Vg = g_VT + (size_t)bh * DHH * SS;
    float* Cp = attn + (size_t)bh * SS * SS;

    // ---- load Q planes (128 x 64 fp16), resident ----
    {
        int r = tid >> 1, c0 = (tid & 1) << 5;       // 2 thr/row, 32 cols each
        const float* p = Qg + (size_t)r * DHH + c0;
        int g = r >> 4, er = (r & 15) >> 3, L = (r & 7) * 4;
        #pragma unroll
        for (int half16 = 0; half16 < 2; half16++) { // two 16-col blocks
            int kb = (c0 >> 4) + half16;
            float4 v0 = *(const float4*)(p + half16 * 16);
            float4 v1 = *(const float4*)(p + half16 * 16 + 4);
            float4 v2 = *(const float4*)(p + half16 * 16 + 8);
            float4 v3 = *(const float4*)(p + half16 * 16 + 12);
            uint4 u0 = make_uint4(h2(v0.x,v0.y), h2(v0.z,v0.w), h2(v1.x,v1.y), h2(v1.z,v1.w));
            uint4 u1 = make_uint4(h2(v2.x,v2.y), h2(v2.z,v2.w), h2(v3.x,v3.y), h2(v3.z,v3.w));
            *(uint4*)&QA[(((er    ) * 8 + g) * 4 + kb) * 32 + L] = u0;
            *(uint4*)&QA[(((er + 2) * 8 + g) * 4 + kb) * 32 + L] = u1;
        }
    }

    // ---- K/V tile loader params (64x64 tiles) ----
    const int rn = tid >> 2;            // 0..63
    const int kb_ld = tid & 3;          // this thread's k-block
    const int gB = rn >> 3, Lb = (rn & 7) * 4;

    // preload tile 0
    unsigned kpa[8], vpa[8];
    {
        const float* kp = Kg + (size_t)rn * DHH + kb_ld * 16;
        const float* vp = Vg + (size_t)rn * SS + kb_ld * 16;
        #pragma unroll
        for (int i = 0; i < 4; i++) {
            float4 t = *(const float4*)(kp + 4 * i);
            kpa[2*i] = h2(t.x, t.y); kpa[2*i+1] = h2(t.z, t.w);
            float4 u = *(const float4*)(vp + 4 * i);
            vpa[2*i] = h2(u.x, u.y); vpa[2*i+1] = h2(u.z, u.w);
        }
        *(uint4*)&KBu[((0 * 8 + gB) * 4 + kb_ld) * 32 + Lb] = make_uint4(kpa[0],kpa[1],kpa[2],kpa[3]);
        *(uint4*)&KBu[((1 * 8 + gB) * 4 + kb_ld) * 32 + Lb] = make_uint4(kpa[4],kpa[5],kpa[6],kpa[7]);
        *(uint4*)&VBu[((0 * 8 + gB) * 4 + kb_ld) * 32 + Lb] = make_uint4(vpa[0],vpa[1],vpa[2],vpa[3]);
        *(uint4*)&VBu[((1 * 8 + gB) * 4 + kb_ld) * 32 + Lb] = make_uint4(vpa[4],vpa[5],vpa[6],vpa[7]);
    }
    __syncthreads();

    float srow[8];
    #pragma unroll
    for (int i = 0; i < 8; i++) srow[i] = 0.f;
    float oacc[4][2][4] = {};

    #pragma unroll 1
    for (int kt = 0; kt < SS / 64; kt++) {
        const int bsel = kt & 1;
        const unsigned* KBc = KBu + bsel * 2048;
        const unsigned* VBc = VBu + bsel * 2048;

        // prefetch next K/V tile into registers (packed half2)
        if (kt + 1 < SS / 64) {
            const float* kp = Kg + (size_t)((kt + 1) * 64 + rn) * DHH + kb_ld * 16;
            const float* vp = Vg + (size_t)rn * SS + (kt + 1) * 64 + kb_ld * 16;
            #pragma unroll
            for (int i = 0; i < 4; i++) {
                float4 t = *(const float4*)(kp + 4 * i);
                kpa[2*i] = h2(t.x, t.y); kpa[2*i+1] = h2(t.z, t.w);
                float4 u = *(const float4*)(vp + 4 * i);
                vpa[2*i] = h2(u.x, u.y); vpa[2*i+1] = h2(u.z, u.w);
            }
        }

        // ---- QK^T mma: acc[4][2][4] ----
        float acc[4][2][4] = {};
        #pragma unroll
        for (int kb = 0; kb < 4; kb++) {
            unsigned a[4][4];
            #pragma unroll
            for (int mt = 0; mt < 4; mt++) {
                int g = wm * 4 + mt;
                a[mt][0] = QA[((0*8+g)*4+kb)*32 + lane];
                a[mt][1] = QA[((1*8+g)*4+kb)*32 + lane];
                a[mt][2] = QA[((2*8+g)*4+kb)*32 + lane];
                a[mt][3] = QA[((3*8+g)*4+kb)*32 + lane];
            }
            unsigned bf[2][2];
            #pragma unroll
            for (int nt = 0; nt < 2; nt++) {
                int g = wn * 2 + nt;
                bf[nt][0] = KBc[((0*8+g)*4+kb)*32 + lane];
                bf[nt][1] = KBc[((1*8+g)*4+kb)*32 + lane];
            }
            #pragma unroll
            for (int mt = 0; mt < 4; mt++)
                #pragma unroll
                for (int nt = 0; nt < 2; nt++)
                    mma16h(acc[mt][nt], a[mt][0], a[mt][1], a[mt][2], a[mt][3],
                           bf[nt][0], bf[nt][1]);
        }

        // ---- epilogue: p = exp(score), attn STG, Ps planes, row sums ----
        #pragma unroll
        for (int mt = 0; mt < 4; mt++) {
            int g = wm * 4 + mt;
            int lr_lo = g * 16 + (lane >> 2);
            int r_lo = m0 + lr_lo;
            int r_hi = r_lo + 8;
            float sl = 0.f, sh = 0.f;
            #pragma unroll
            for (int nt = 0; nt < 2; nt++) {
                int cl = wn * 16 + nt * 8 + 2 * (lane & 3);
                int cn = kt * 64 + cl;
                int2 mm0 = *(const int2*)(mask + (size_t)r_lo * SS + cn);
                int2 mm1 = *(const int2*)(mask + (size_t)r_hi * SS + cn);
                float p0 = mm0.x ? __expf(acc[mt][nt][0] * 0.125f) : 0.f;
                float p1 = mm0.y ? __expf(acc[mt][nt][1] * 0.125f) : 0.f;
                float p2 = mm1.x ? __expf(acc[mt][nt][2] * 0.125f) : 0.f;
                float p3 = mm1.y ? __expf(acc[mt][nt][3] * 0.125f) : 0.f;
                *(float2*)(Cp + (size_t)r_lo * SS + cn) = make_float2(p0, p1);
                *(float2*)(Cp + (size_t)r_hi * SS + cn) = make_float2(p2, p3);
                Ps[(((2*nt    )*8 + g)*4 + wn)*32 + lane] = h2(p0, p1);
                Ps[(((2*nt + 1)*8 + g)*4 + wn)*32 + lane] = h2(p2, p3);
                sl += p0 + p1; sh += p2 + p3;
            }
            srow[mt*2]     += sl;
            srow[mt*2 + 1] += sh;
        }
        __syncthreads();   // Ps visible to all warps

        // ---- O += P . V ----
        #pragma unroll
        for (int kb = 0; kb < 4; kb++) {
            unsigned a[4][4];
            #pragma unroll
            for (int mt = 0; mt < 4; mt++) {
                int g = wm * 4 + mt;
                a[mt][0] = Ps[((0*8+g)*4+kb)*32 + lane];
                a[mt][1] = Ps[((1*8+g)*4+kb)*32 + lane];
                a[mt][2] = Ps[((2*8+g)*4+kb)*32 + lane];
                a[mt][3] = Ps[((3*8+g)*4+kb)*32 + lane];
            }
            unsigned bf[2][2];
            #pragma unroll
            for (int nt = 0; nt < 2; nt++) {
                int g = wn * 2 + nt;
                bf[nt][0] = VBc[((0*8+g)*4+kb)*32 + lane];
                bf[nt][1] = VBc[((1*8+g)*4+kb)*32 + lane];
            }
            #pragma unroll
            for (int mt = 0; mt < 4; mt++)
                #pragma unroll
                for (int nt = 0; nt < 2; nt++)
                    mma16h(oacc[mt][nt], a[mt][0], a[mt][1], a[mt][2], a[mt][3],
                           bf[nt][0], bf[nt][1]);
        }

        // store prefetched tile into the other buffer
        if (kt + 1 < SS / 64) {
            unsigned* KBn = KBu + (bsel ^ 1) * 2048;
            unsigned* VBn = VBu + (bsel ^ 1) * 2048;
            *(uint4*)&KBn[((0*8+gB)*4+kb_ld)*32 + Lb] = make_uint4(kpa[0],kpa[1],kpa[2],kpa[3]);
            *(uint4*)&KBn[((1*8+gB)*4+kb_ld)*32 + Lb] = make_uint4(kpa[4],kpa[5],kpa[6],kpa[7]);
            *(uint4*)&VBn[((0*8+gB)*4+kb_ld)*32 + Lb] = make_uint4(vpa[0],vpa[1],vpa[2],vpa[3]);
            *(uint4*)&VBn[((1*8+gB)*4+kb_ld)*32 + Lb] = make_uint4(vpa[4],vpa[5],vpa[6],vpa[7]);
        }
        __syncthreads();   // next buffers ready; Ps safe to overwrite next iter
    }

    // ---- reduce row sums: 4 lanes sharing each row, then 4 wn warps ----
    #pragma unroll
    for (int o = 1; o <= 2; o <<= 1)
        #pragma unroll
        for (int i = 0; i < 8; i++)
            srow[i] += __shfl_xor_sync(0xffffffffu, srow[i], o);

    if ((lane & 3) == 0) {
        #pragma unroll
        for (int i = 0; i < 8; i++) {
            int lr = wm * 64 + (i >> 1) * 16 + (lane >> 2) + (i & 1) * 8;
            red[wn * 128 + lr] = srow[i];
        }
    }
    __syncthreads();
    if (wn == 0 && (lane & 3) == 0) {
        #pragma unroll
        for (int i = 0; i < 8; i++) {
            int lr = wm * 64 + (i >> 1) * 16 + (lane >> 2) + (i & 1) * 8;
            float s = red[lr] + red[128 + lr] + red[256 + lr] + red[384 + lr];
            float inv = 1.0f / s;
            sF[lr] = inv;
            g_S[(size_t)bh * SS + m0 + lr] = inv;
        }
    }
    __syncthreads();

    // ---- O epilogue (normalized) -> g_O [B,S,D] ----
    const int b = bh >> 4, h = bh & 15;
    #pragma unroll
    for (int mt = 0; mt < 4; mt++) {
        int lr_lo = wm * 64 + mt * 16 + (lane >> 2);
        int s_lo = m0 + lr_lo;
        int s_hi = s_lo + 8;
        float inv0 = sF[lr_lo], inv1 = sF[lr_lo + 8];
        #pragma unroll
        for (int nt = 0; nt < 2; nt++) {
            int n = wn * 16 + nt * 8 + 2 * (lane & 3);
            *(float2*)&g_O[((size_t)(b * SS + s_lo)) * DD + h * DHH + n] =
                make_float2(oacc[mt][nt][0] * inv0, oacc[mt][nt][1] * inv0);
            *(float2*)&g_O[((size_t)(b * SS + s_hi)) * DD + h * DHH + n] =
                make_float2(oacc[mt][nt][2] * inv1, oacc[mt][nt][3] * inv1);
        }
    }
}

// ---------------------------------------------------------------------------
// attn normalization: attn[row] *= g_S[row]  (g_S holds 1/s)
// ---------------------------------------------------------------------------
__global__ __launch_bounds__(256) void scale_kernel(float* __restrict__ attn)
{
    const size_t row = blockIdx.x;
    const float inv = g_S[row];
    float* p = attn + row * SS;
    const int tid = threadIdx.x;
    float4 v0 = ((float4*)p)[tid];
    float4 v1 = ((float4*)p)[tid + 256];
    v0.x *= inv; v0.y *= inv; v0.z *= inv; v0.w *= inv;
    v1.x *= inv; v1.y *= inv; v1.z *= inv; v1.w *= inv;
    ((float4*)p)[tid]       = v0;
    ((float4*)p)[tid + 256] = v1;
}

// ===========================================================================
// GEMM core for projections / output (tf32, unchanged from R6)
// ===========================================================================
struct __align__(16) Smem {
    unsigned A[2][4][8][4][32];
    unsigned B[2][2][8][4][32];
};

__device__ __forceinline__ void stsA(Smem& S, int buf, int r, int cbase, const float4* v) {
    const int g    = r >> 4;
    const int rr   = r & 15;
    const int Lb   = (rr & 7) * 4;
    const int erow = rr >> 3;
    #pragma unroll
    for (int i = 0; i < 4; i++) {
        const int c  = cbase + 4 * i;
        const int ks = c >> 3;
        const int e  = erow + ((c & 4) >> 1);
        uint4 u;
        u.x = f2tf(v[i].x); u.y = f2tf(v[i].y); u.z = f2tf(v[i].z); u.w = f2tf(v[i].w);
        *(uint4*)&S.A[buf][e][g][ks][Lb] = u;
    }
}

__device__ __forceinline__ void stsB(Smem& S, int buf, int n, int cbase, const float4* v) {
    const int g  = n >> 3;
    const int Lb = (n & 7) * 4;
    #pragma unroll
    for (int i = 0; i < 2; i++) {
        const int c  = cbase + 4 * i;
        const int ks = c >> 3;
        const int e  = (c & 4) >> 2;
        uint4 u;
        u.x = f2tf(v[i].x); u.y = f2tf(v[i].y); u.z = f2tf(v[i].z); u.w = f2tf(v[i].w);
        *(uint4*)&S.B[buf][e][g][ks][Lb] = u;
    }
}

__device__ __forceinline__ void mma_step(const Smem& S, int buf, int lane, int wm, int wn,
                                         float (*acc)[2][4]) {
    #pragma unroll
    for (int ks = 0; ks < 4; ks++) {
        unsigned a[4][4];
        #pragma unroll
        for (int mt = 0; mt < 4; mt++) {
            const int g = wm * 4 + mt;
            a[mt][0] = S.A[buf][0][g][ks][lane];
            a[mt][1] = S.A[buf][1][g][ks][lane];
            a[mt][2] = S.A[buf][2][g][ks][lane];
            a[mt][3] = S.A[buf][3][g][ks][lane];
        }
        unsigned b[2][2];
        #pragma unroll
        for (int nt = 0; nt < 2; nt++) {
            const int g = wn * 2 + nt;
            b[nt][0] = S.B[buf][0][g][ks][lane];
            b[nt][1] = S.B[buf][1][g][ks][lane];
        }
        #pragma unroll
        for (int mt = 0; mt < 4; mt++)
            #pragma unroll
            for (int nt = 0; nt < 2; nt++)
                mma8(acc[mt][nt], a[mt][0], a[mt][1], a[mt][2], a[mt][3],
                     b[nt][0], b[nt][1]);
    }
}

template<int KB_>
__device__ __forceinline__ void gemm_core(
    const float* __restrict__ Ag, int lda,
    const float* __restrict__ Bg, int ldb,
    Smem& S, float (*acc)[2][4])
{
    const int tid  = threadIdx.x;
    const int lane = tid & 31;
    const int warp = tid >> 5;
    const int wm = warp & 1;
    const int wn = warp >> 1;

    const int ar = tid >> 1, ac = (tid & 1) << 4;
    const int br = tid >> 2, bc = (tid & 3) << 3;
    const float* Ap = Ag + (size_t)ar * lda + ac;
    const float* Bp = Bg + (size_t)br * ldb + bc;

    float4 aL[4], bL[2];
    #pragma unroll
    for (int i = 0; i < 4; i++) aL[i] = *(const float4*)(Ap + 4 * i);
    #pragma unroll
    for (int i = 0; i < 2; i++) bL[i] = *(const float4*)(Bp + 4 * i);
    stsA(S, 0, ar, ac, aL);
    stsB(S, 0, br, bc, bL);
    __syncthreads();

    #pragma unroll 2
    for (int kb = 1; kb < KB_; kb++) {
        #pragma unroll
        for (int i = 0; i < 4; i++) aL[i] = *(const float4*)(Ap + kb * 32 + 4 * i);
        #pragma unroll
        for (int i = 0; i < 2; i++) bL[i] = *(const float4*)(Bp + kb * 32 + 4 * i);
        mma_step(S, (kb - 1) & 1, lane, wm, wn, acc);
        stsA(S, kb & 1, ar, ac, aL);
        stsB(S, kb & 1, br, bc, bL);
        __syncthreads();
    }
    mma_step(S, (KB_ - 1) & 1, lane, wm, wn, acc);
}

// ---------------------------------------------------------------------------
__global__ __launch_bounds__(256, 2) void proj_kernel(
    const float* __restrict__ X, const float* __restrict__ W, int which)
{
    __shared__ Smem S;
    const int m0 = blockIdx.y * 128;
    const int n0 = blockIdx.x * 64;
    float acc[4][2][4] = {};
    gemm_core<DD/32>(X + (size_t)m0 * DD, DD, W + (size_t)n0 * DD, DD, S, acc);

    const int tid = threadIdx.x, lane = tid & 31, warp = tid >> 5;
    const int wm = warp & 1, wn = warp >> 1;
    #pragma unroll
    for (int mt = 0; mt < 4; mt++) {
        int m_lo = m0 + wm * 64 + mt * 16 + (lane >> 2);
        int m_hi = m_lo + 8;
        int b_lo = m_lo >> 11, s_lo = m_lo & (SS - 1);
        int b_hi = m_hi >> 11, s_hi = m_hi & (SS - 1);
        #pragma unroll
        for (int nt = 0; nt < 2; nt++) {
            int cn = n0 + wn * 16 + nt * 8 + 2 * (lane & 3);
            int h = cn >> 6, d = cn & 63;
            float c0 = acc[mt][nt][0], c1 = acc[mt][nt][1];
            float c2 = acc[mt][nt][2], c3 = acc[mt][nt][3];
            if (which == 2) {
                g_VT[((size_t)((b_lo*HH + h)*DHH + d    )) * SS + s_lo] = c0;
                g_VT[((size_t)((b_lo*HH + h)*DHH + d + 1)) * SS + s_lo] = c1;
                g_VT[((size_t)((b_hi*HH + h)*DHH + d    )) * SS + s_hi] = c2;
                g_VT[((size_t)((b_hi*HH + h)*DHH + d + 1)) * SS + s_hi] = c3;
            } else {
                float* dst = (which == 0) ? g_QH : g_KH;
                *(float2*)&dst[(((size_t)(b_lo*HH + h)*SS + s_lo) << 6) + d] = make_float2(c0, c1);
                *(float2*)&dst[(((size_t)(b_hi*HH + h)*SS + s_hi) << 6) + d] = make_float2(c2, c3);
            }
        }
    }
}

// ---------------------------------------------------------------------------
__global__ __launch_bounds__(256, 2) void out_kernel(
    const float* __restrict__ Wo, float* __restrict__ out)
{
    __shared__ Smem S;
    const int m0 = blockIdx.y * 128;
    const int n0 = blockIdx.x * 64;
    float acc[4][2][4] = {};
    gemm_core<DD/32>(g_O + (size_t)m0 * DD, DD, Wo + (size_t)n0 * DD, DD, S, acc);

    const int tid = threadIdx.x, lane = tid & 31, warp = tid >> 5;
    const int wm = warp & 1, wn = warp >> 1;
    #pragma unroll
    for (int mt = 0; mt < 4; mt++) {
        int m_lo = m0 + wm * 64 + mt * 16 + (lane >> 2);
        int m_hi = m_lo + 8;
        #pragma unroll
        for (int nt = 0; nt < 2; nt++) {
            int cn = n0 + wn * 16 + nt * 8 + 2 * (lane & 3);
            *(float2*)(out + (size_t)m_lo * DD + cn) =
                make_float2(acc[mt][nt][0], acc[mt][nt][1]);
            *(float2*)(out + (size_t)m_hi * DD + cn) =
                make_float2(acc[mt][nt][2], acc[mt][nt][3]);
        }
    }
}

// ---------------------------------------------------------------------------
extern "C" void kernel_launch(void* const* d_in, const int* in_sizes, int n_in,
                              void* d_out, int out_size)
{
    const float* q    = (const float*)d_in[0];
    const float* k    = (const float*)d_in[1];
    const float* v    = (const float*)d_in[2];
    const int*   mask = (const int*)  d_in[3];
    const float* Wq   = (const float*)d_in[4];
    const float* Wk   = (const float*)d_in[5];
    const float* Wv   = (const float*)d_in[6];
    const float* Wo   = (const float*)d_in[7];

    float* out  = (float*)d_out;
    float* attn = out + (size_t)BB * SS * DD;   // out first, then attn

    static int smem_set = 0;
    if (!smem_set) {
        cudaFuncSetAttribute(fused_attn_kernel,
                             cudaFuncAttributeMaxDynamicSharedMemorySize, SMEM_FUSED);
        smem_set = 1;
    }

    dim3 blk(256);
    dim3 gp(DD / 64, (BB * SS) / 128);          // 16 x 32
    proj_kernel<<<gp, blk>>>(q, Wq, 0);
    proj_kernel<<<gp, blk>>>(k, Wk, 1);
    proj_kernel<<<gp, blk>>>(v, Wv, 2);

    fused_attn_kernel<<<dim3(SS / 128, BB * HH), blk, SMEM_FUSED>>>(mask, attn);

    scale_kernel<<<BB * HH * SS, blk>>>(attn);

    out_kernel<<<gp, blk>>>(Wo, out);
}